// round 9
// baseline (speedup 1.0000x reference)
#include <cuda_runtime.h>
#include <math.h>

// Problem constants
#define NBATCH 8
#define NPTS   2048
#define NFEAT  32
#define NROWS  (NBATCH * NPTS)                       // 16384
#define NMAT   ((size_t)NBATCH * NPTS * NPTS)        // 33554432
#define MAX_IT 100

// eps = 0.1 ; log2-domain scale: (1/eps) * log2(e)
#define S2   14.4269504088896341f
#define LN2  0.6931471805599453f
#define EPSV 0.1f
#define LOG_MUV (logf(1.0f / 2048.0f + 1e-8f))      // == log_nu (N == M)
#define ERR_THRESH_SUM 0.8f

// Scratch (__device__ globals; no allocation allowed)
__device__ __align__(16) float g_u[NROWS];
__device__ __align__(16) float g_v[NROWS];
__device__ float g_err[MAX_IT];
__device__ __align__(16) float g_ct[NMAT];           // 128 MB transposed cost

__device__ __forceinline__ float ex2f(float x) {
    float y;
    asm("ex2.approx.ftz.f32 %0, %1;" : "=f"(y) : "f"(x));
    return y;
}
__device__ __forceinline__ float lg2f(float x) {
    float y;
    asm("lg2.approx.ftz.f32 %0, %1;" : "=f"(y) : "f"(x));
    return y;
}

// ---------------------------------------------------------------------------
// Init
// ---------------------------------------------------------------------------
__global__ void k_init(float* __restrict__ cost) {
    int t = blockIdx.x * blockDim.x + threadIdx.x;
    int n = gridDim.x * blockDim.x;
    for (int i = t; i < NROWS; i += n) {
        g_u[i] = 0.0f;
        g_v[i] = 0.0f;
    }
    if (t < MAX_IT) g_err[t] = 0.0f;
    if (t < NBATCH) cost[t] = 0.0f;
}

// Dummy no-op: keeps the ncu capture slot aligned onto k_sweep.
__global__ void k_dummy() {}

// ---------------------------------------------------------------------------
// Cost matrix: C[b,i,j] = sum_d (x[b,i,d] - y[b,j,d])^2 ; also writes CT = C^T.
// ---------------------------------------------------------------------------
__global__ void __launch_bounds__(256) k_cost(const float* __restrict__ x,
                                              const float* __restrict__ y,
                                              float* __restrict__ C) {
    __shared__ float xs[NFEAT * 65];
    __shared__ float ys[NFEAT * 65];

    int tile = blockIdx.x;          // 8192 tiles of 64x64
    int b  = tile >> 10;
    int ti = (tile >> 5) & 31;
    int tj = tile & 31;
    int tid = threadIdx.x;

    const float* xb = x + ((size_t)b * NPTS + (size_t)ti * 64) * NFEAT;
    const float* yb = y + ((size_t)b * NPTS + (size_t)tj * 64) * NFEAT;

    for (int e = tid; e < 64 * NFEAT; e += 256) {
        int row = e >> 5;
        int d   = e & 31;
        xs[d * 65 + row] = xb[e];
        ys[d * 65 + row] = yb[e];
    }
    __syncthreads();

    int ri = (tid >> 4) << 2;
    int cj = (tid & 15) << 2;

    float acc[4][4];
#pragma unroll
    for (int a = 0; a < 4; a++)
#pragma unroll
        for (int c = 0; c < 4; c++) acc[a][c] = 0.0f;

#pragma unroll
    for (int d = 0; d < NFEAT; d++) {
        float xa[4], yv[4];
#pragma unroll
        for (int a = 0; a < 4; a++) xa[a] = xs[d * 65 + ri + a];
#pragma unroll
        for (int c = 0; c < 4; c++) yv[c] = ys[d * 65 + cj + c];
#pragma unroll
        for (int a = 0; a < 4; a++)
#pragma unroll
            for (int c = 0; c < 4; c++) {
                float diff = xa[a] - yv[c];
                acc[a][c] = fmaf(diff, diff, acc[a][c]);
            }
    }

    float* Cb = C + (size_t)b * NPTS * NPTS + (size_t)(ti * 64 + ri) * NPTS + (tj * 64 + cj);
#pragma unroll
    for (int a = 0; a < 4; a++) {
        float4 o = make_float4(acc[a][0], acc[a][1], acc[a][2], acc[a][3]);
        *reinterpret_cast<float4*>(Cb + (size_t)a * NPTS) = o;
    }

    // transposed copy: CT[b, j, i] = C[b, i, j]
    float* Tb = g_ct + (size_t)b * NPTS * NPTS + (size_t)(tj * 64 + cj) * NPTS + (ti * 64 + ri);
#pragma unroll
    for (int c = 0; c < 4; c++) {
        float4 o = make_float4(acc[0][c], acc[1][c], acc[2][c], acc[3][c]);
        *reinterpret_cast<float4*>(Tb + (size_t)c * NPTS) = o;
    }
}

// ---------------------------------------------------------------------------
// One Sinkhorn half-step (generic over u/v by pointer swap):
//   mine[r] = eps * (log_mu - lse_j((oth[j] - M[r, j]) / eps))
// M row-major for this sweep (C for the u-pass, CT for the v-pass).
// Block = 256 threads (8 warps), 2 ADJACENT ROWS PER WARP (16 rows/block):
//   - 4 LDG.128 in flight per unrolled step (vs 2), 4 independent LSE chains
//   - smem v loads shared between the two rows
//   - no inter-warp sync in the hot path
// track_err != 0: accumulate sum |mine_new - mine_old| into g_err[it].
// Early freeze: g_err[it-1] < thresh (sticky; frozen iters leave g_err = 0).
// ---------------------------------------------------------------------------
__global__ void __launch_bounds__(256) k_sweep(const float* __restrict__ M,
                                               const float* __restrict__ oth,
                                               float* __restrict__ mine,
                                               int it, int track_err) {
    if (it > 0 && g_err[it - 1] < ERR_THRESH_SUM) return;

    __shared__ float oS2[NPTS];          // 8 KB : other potential * S2
    __shared__ float blkerr;

    int blk = blockIdx.x;                // 1024 blocks, 16 rows each
    int b   = blk >> 7;
    int tid = threadIdx.x;
    int w   = tid >> 5;
    int l   = tid & 31;

    const float4* og  = reinterpret_cast<const float4*>(oth + (b << 11));
    float4*       os4 = reinterpret_cast<float4*>(oS2);
#pragma unroll
    for (int k = 0; k < 2; k++) {
        float4 t = og[tid + (k << 8)];
        t.x *= S2; t.y *= S2; t.z *= S2; t.w *= S2;
        os4[tid + (k << 8)] = t;
    }
    if (tid == 0) blkerr = 0.0f;
    __syncthreads();

    int r0 = (blk << 4) + (w << 1);      // two adjacent global rows
    int r1 = r0 + 1;
    const float4* M0 = reinterpret_cast<const float4*>(M + ((size_t)r0 << 11));
    const float4* M1 = reinterpret_cast<const float4*>(M + ((size_t)r1 << 11));

    // dual online-LSE chains per row -> 4 independent chains
    float am0 = -1e30f, as0 = 0.0f, bm0 = -1e30f, bs0 = 0.0f;   // row 0
    float am1 = -1e30f, as1 = 0.0f, bm1 = -1e30f, bs1 = 0.0f;   // row 1
#pragma unroll
    for (int g = 0; g < 8; g++) {
        int idx = l + (g << 6);
        float4 c00 = M0[idx];
        float4 c01 = M0[idx + 32];
        float4 c10 = M1[idx];
        float4 c11 = M1[idx + 32];
        float4 v0 = os4[idx];
        float4 v1 = os4[idx + 32];

        // row 0, chain A (first 4) and chain B (second 4)
        {
            float t0 = fmaf(-S2, c00.x, v0.x);
            float t1 = fmaf(-S2, c00.y, v0.y);
            float t2 = fmaf(-S2, c00.z, v0.z);
            float t3 = fmaf(-S2, c00.w, v0.w);
            float mA = fmaxf(fmaxf(t0, t1), fmaxf(t2, t3));
            float n  = fmaxf(am0, mA);
            as0 = as0 * ex2f(am0 - n)
                + ((ex2f(t0 - n) + ex2f(t1 - n)) + (ex2f(t2 - n) + ex2f(t3 - n)));
            am0 = n;
            float t4 = fmaf(-S2, c01.x, v1.x);
            float t5 = fmaf(-S2, c01.y, v1.y);
            float t6 = fmaf(-S2, c01.z, v1.z);
            float t7 = fmaf(-S2, c01.w, v1.w);
            float mB = fmaxf(fmaxf(t4, t5), fmaxf(t6, t7));
            float nb = fmaxf(bm0, mB);
            bs0 = bs0 * ex2f(bm0 - nb)
                + ((ex2f(t4 - nb) + ex2f(t5 - nb)) + (ex2f(t6 - nb) + ex2f(t7 - nb)));
            bm0 = nb;
        }
        // row 1
        {
            float t0 = fmaf(-S2, c10.x, v0.x);
            float t1 = fmaf(-S2, c10.y, v0.y);
            float t2 = fmaf(-S2, c10.z, v0.z);
            float t3 = fmaf(-S2, c10.w, v0.w);
            float mA = fmaxf(fmaxf(t0, t1), fmaxf(t2, t3));
            float n  = fmaxf(am1, mA);
            as1 = as1 * ex2f(am1 - n)
                + ((ex2f(t0 - n) + ex2f(t1 - n)) + (ex2f(t2 - n) + ex2f(t3 - n)));
            am1 = n;
            float t4 = fmaf(-S2, c11.x, v1.x);
            float t5 = fmaf(-S2, c11.y, v1.y);
            float t6 = fmaf(-S2, c11.z, v1.z);
            float t7 = fmaf(-S2, c11.w, v1.w);
            float mB = fmaxf(fmaxf(t4, t5), fmaxf(t6, t7));
            float nb = fmaxf(bm1, mB);
            bs1 = bs1 * ex2f(bm1 - nb)
                + ((ex2f(t4 - nb) + ex2f(t5 - nb)) + (ex2f(t6 - nb) + ex2f(t7 - nb)));
            bm1 = nb;
        }
    }
    // merge chains per row
    float m0 = fmaxf(am0, bm0);
    float s0 = as0 * ex2f(am0 - m0) + bs0 * ex2f(bm0 - m0);
    float m1 = fmaxf(am1, bm1);
    float s1 = as1 * ex2f(am1 - m1) + bs1 * ex2f(bm1 - m1);
    // interleaved warp reductions (both rows in one shuffle loop for ILP)
#pragma unroll
    for (int o = 16; o; o >>= 1) {
        float m0o = __shfl_xor_sync(0xffffffffu, m0, o);
        float s0o = __shfl_xor_sync(0xffffffffu, s0, o);
        float m1o = __shfl_xor_sync(0xffffffffu, m1, o);
        float s1o = __shfl_xor_sync(0xffffffffu, s1, o);
        float n0 = fmaxf(m0, m0o);
        s0 = s0 * ex2f(m0 - n0) + s0o * ex2f(m0o - n0);
        m0 = n0;
        float n1 = fmaxf(m1, m1o);
        s1 = s1 * ex2f(m1 - n1) + s1o * ex2f(m1o - n1);
        m1 = n1;
    }
    if (l == 0) {
        float p0 = EPSV * (LOG_MUV - (m0 + lg2f(s0)) * LN2);
        float p1 = EPSV * (LOG_MUV - (m1 + lg2f(s1)) * LN2);
        if (track_err) {
            float du = fabsf(p0 - mine[r0]) + fabsf(p1 - mine[r1]);
            atomicAdd(&blkerr, du);
        }
        mine[r0] = p0;
        mine[r1] = p1;
    }
    if (track_err) {
        __syncthreads();
        if (tid == 0) atomicAdd(&g_err[it], blkerr);
    }
}

// ---------------------------------------------------------------------------
// Epilogue: pi = exp((u_i + v_j - C_ij)/eps), cost[b] = sum pi*C
// ---------------------------------------------------------------------------
__global__ void __launch_bounds__(256) k_pi(const float* __restrict__ C,
                                            float* __restrict__ pi,
                                            float* __restrict__ cost) {
    __shared__ float blkcost;
    if (threadIdx.x == 0) blkcost = 0.0f;
    __syncthreads();

    int warp = (blockIdx.x << 3) + (threadIdx.x >> 5);
    int lane = threadIdx.x & 31;
    int r = warp;
    int b = r >> 11;

    float u = g_u[r];
    const float4* Cr = reinterpret_cast<const float4*>(C + (size_t)r * NPTS);
    const float4* Vr = reinterpret_cast<const float4*>(g_v + (b << 11));
    float4* Pr = reinterpret_cast<float4*>(pi + (size_t)r * NPTS);

    float acc = 0.0f;
#pragma unroll 4
    for (int k = lane; k < NPTS / 4; k += 32) {
        float4 c = Cr[k];
        float4 v = Vr[k];
        float4 p;
        p.x = ex2f((u + v.x - c.x) * S2);
        p.y = ex2f((u + v.y - c.y) * S2);
        p.z = ex2f((u + v.z - c.z) * S2);
        p.w = ex2f((u + v.w - c.w) * S2);
        Pr[k] = p;
        acc += p.x * c.x + p.y * c.y + p.z * c.z + p.w * c.w;
    }
#pragma unroll
    for (int o = 16; o; o >>= 1) acc += __shfl_xor_sync(0xffffffffu, acc, o);
    if (lane == 0) atomicAdd(&blkcost, acc);
    __syncthreads();
    if (threadIdx.x == 0) atomicAdd(&cost[b], blkcost);
}

// ---------------------------------------------------------------------------
// Launch: init -> cost(+CT) -> dummy -> 100 x (u-sweep over C, v-sweep over CT)
// -> pi. Output layout (tuple order): cost[8] | pi | C.
// ---------------------------------------------------------------------------
extern "C" void kernel_launch(void* const* d_in, const int* in_sizes, int n_in,
                              void* d_out, int out_size) {
    const float* x = (const float*)d_in[0];
    const float* y = (const float*)d_in[1];
    float* out  = (float*)d_out;
    float* cost = out;
    float* pi   = out + NBATCH;
    float* C    = out + NBATCH + NMAT;

    float* ct;
    cudaGetSymbolAddress((void**)&ct, g_ct);
    float* u;
    cudaGetSymbolAddress((void**)&u, g_u);
    float* v;
    cudaGetSymbolAddress((void**)&v, g_v);

    k_init<<<64, 256>>>(cost);
    k_cost<<<NBATCH * 32 * 32, 256>>>(x, y, C);
    k_dummy<<<1, 32>>>();   // keeps ncu capture slot on k_sweep
    for (int it = 0; it < MAX_IT; it++) {
        k_sweep<<<NROWS / 16, 256>>>(C,  v, u, it, 1);   // u update (tracks err)
        k_sweep<<<NROWS / 16, 256>>>(ct, u, v, it, 0);   // v update
    }
    k_pi<<<NROWS / 8, 256>>>(C, pi, cost);
}

// round 10
// speedup vs baseline: 1.1528x; 1.1528x over previous
#include <cuda_runtime.h>
#include <math.h>

// Problem constants
#define NBATCH 8
#define NPTS   2048
#define NFEAT  32
#define NROWS  (NBATCH * NPTS)                       // 16384
#define NMAT   ((size_t)NBATCH * NPTS * NPTS)        // 33554432
#define MAX_IT 100

// eps = 0.1 ; log2-domain scale: (1/eps) * log2(e)
#define S2   14.4269504088896341f
#define LN2  0.6931471805599453f
#define EPSV 0.1f
#define LOG_MUV (logf(1.0f / 2048.0f + 1e-8f))      // == log_nu (N == M)
#define ERR_THRESH_SUM 0.8f

// Scratch (__device__ globals; no allocation allowed)
__device__ __align__(16) float g_u[NROWS];
__device__ __align__(16) float g_v[NROWS];
__device__ float g_err[MAX_IT];
__device__ __align__(16) float g_ct[NMAT];           // 128 MB transposed cost

__device__ __forceinline__ float ex2f(float x) {
    float y;
    asm("ex2.approx.ftz.f32 %0, %1;" : "=f"(y) : "f"(x));
    return y;
}
__device__ __forceinline__ float lg2f(float x) {
    float y;
    asm("lg2.approx.ftz.f32 %0, %1;" : "=f"(y) : "f"(x));
    return y;
}

// ---------------------------------------------------------------------------
// Init
// ---------------------------------------------------------------------------
__global__ void k_init(float* __restrict__ cost) {
    int t = blockIdx.x * blockDim.x + threadIdx.x;
    int n = gridDim.x * blockDim.x;
    for (int i = t; i < NROWS; i += n) {
        g_u[i] = 0.0f;
        g_v[i] = 0.0f;
    }
    if (t < MAX_IT) g_err[t] = 0.0f;
    if (t < NBATCH) cost[t] = 0.0f;
}

// Dummy no-op: keeps the ncu capture slot aligned onto k_sweep.
__global__ void k_dummy() {}

// ---------------------------------------------------------------------------
// Cost matrix: C[b,i,j] = sum_d (x[b,i,d] - y[b,j,d])^2 ; also writes CT = C^T.
// ---------------------------------------------------------------------------
__global__ void __launch_bounds__(256) k_cost(const float* __restrict__ x,
                                              const float* __restrict__ y,
                                              float* __restrict__ C) {
    __shared__ float xs[NFEAT * 65];
    __shared__ float ys[NFEAT * 65];

    int tile = blockIdx.x;          // 8192 tiles of 64x64
    int b  = tile >> 10;
    int ti = (tile >> 5) & 31;
    int tj = tile & 31;
    int tid = threadIdx.x;

    const float* xb = x + ((size_t)b * NPTS + (size_t)ti * 64) * NFEAT;
    const float* yb = y + ((size_t)b * NPTS + (size_t)tj * 64) * NFEAT;

    for (int e = tid; e < 64 * NFEAT; e += 256) {
        int row = e >> 5;
        int d   = e & 31;
        xs[d * 65 + row] = xb[e];
        ys[d * 65 + row] = yb[e];
    }
    __syncthreads();

    int ri = (tid >> 4) << 2;
    int cj = (tid & 15) << 2;

    float acc[4][4];
#pragma unroll
    for (int a = 0; a < 4; a++)
#pragma unroll
        for (int c = 0; c < 4; c++) acc[a][c] = 0.0f;

#pragma unroll
    for (int d = 0; d < NFEAT; d++) {
        float xa[4], yv[4];
#pragma unroll
        for (int a = 0; a < 4; a++) xa[a] = xs[d * 65 + ri + a];
#pragma unroll
        for (int c = 0; c < 4; c++) yv[c] = ys[d * 65 + cj + c];
#pragma unroll
        for (int a = 0; a < 4; a++)
#pragma unroll
            for (int c = 0; c < 4; c++) {
                float diff = xa[a] - yv[c];
                acc[a][c] = fmaf(diff, diff, acc[a][c]);
            }
    }

    float* Cb = C + (size_t)b * NPTS * NPTS + (size_t)(ti * 64 + ri) * NPTS + (tj * 64 + cj);
#pragma unroll
    for (int a = 0; a < 4; a++) {
        float4 o = make_float4(acc[a][0], acc[a][1], acc[a][2], acc[a][3]);
        *reinterpret_cast<float4*>(Cb + (size_t)a * NPTS) = o;
    }

    // transposed copy: CT[b, j, i] = C[b, i, j]
    float* Tb = g_ct + (size_t)b * NPTS * NPTS + (size_t)(tj * 64 + cj) * NPTS + (ti * 64 + ri);
#pragma unroll
    for (int c = 0; c < 4; c++) {
        float4 o = make_float4(acc[0][c], acc[1][c], acc[2][c], acc[3][c]);
        *reinterpret_cast<float4*>(Tb + (size_t)c * NPTS) = o;
    }
}

// ---------------------------------------------------------------------------
// One Sinkhorn half-step (generic over u/v by pointer swap):
//   mine[r] = eps * (log_mu - lse_j((oth[j] - M[r, j]) / eps))
// M row-major for this sweep (C for the u-pass, CT for the v-pass).
// Block = 256 threads (8 warps), WARP PER ROW (R8 shape), but each unrolled
// step issues 4 back-to-back streaming LDG.128 (__ldcs, no L1 allocate)
// feeding 4 INDEPENDENT online-LSE chains -> 2x loads in flight per warp.
// track_err != 0: accumulate sum |mine_new - mine_old| into g_err[it].
// Early freeze: g_err[it-1] < thresh (sticky; frozen iters leave g_err = 0).
// ---------------------------------------------------------------------------
__global__ void __launch_bounds__(256) k_sweep(const float* __restrict__ M,
                                               const float* __restrict__ oth,
                                               float* __restrict__ mine,
                                               int it, int track_err) {
    if (it > 0 && g_err[it - 1] < ERR_THRESH_SUM) return;

    __shared__ float oS2[NPTS];          // 8 KB : other potential * S2
    __shared__ float blkerr;

    int blk = blockIdx.x;                // 2048 blocks, 8 rows each
    int b   = blk >> 8;
    int tid = threadIdx.x;
    int w   = tid >> 5;
    int l   = tid & 31;

    const float4* og  = reinterpret_cast<const float4*>(oth + (b << 11));
    float4*       os4 = reinterpret_cast<float4*>(oS2);
#pragma unroll
    for (int k = 0; k < 2; k++) {
        float4 t = og[tid + (k << 8)];
        t.x *= S2; t.y *= S2; t.z *= S2; t.w *= S2;
        os4[tid + (k << 8)] = t;
    }
    if (tid == 0) blkerr = 0.0f;
    __syncthreads();

    int r = (blk << 3) + w;              // global row index
    const float4* Mr = reinterpret_cast<const float4*>(M + ((size_t)r << 11));

    // 4 independent online-LSE chains (one per quarter of each 512-col step)
    float cm[4] = {-1e30f, -1e30f, -1e30f, -1e30f};
    float cs[4] = {0.0f, 0.0f, 0.0f, 0.0f};

#pragma unroll
    for (int g = 0; g < 4; g++) {
        int idx = l + (g << 7);          // float4 index, stride 128 per step
        // 4 streaming loads issued back-to-back before any compute
        float4 c0 = __ldcs(&Mr[idx]);
        float4 c1 = __ldcs(&Mr[idx + 32]);
        float4 c2 = __ldcs(&Mr[idx + 64]);
        float4 c3 = __ldcs(&Mr[idx + 96]);
        float4 v0 = os4[idx];
        float4 v1 = os4[idx + 32];
        float4 v2 = os4[idx + 64];
        float4 v3 = os4[idx + 96];

#define CHAIN(q, cc, vv)                                                       \
        {                                                                      \
            float t0 = fmaf(-S2, (cc).x, (vv).x);                              \
            float t1 = fmaf(-S2, (cc).y, (vv).y);                              \
            float t2 = fmaf(-S2, (cc).z, (vv).z);                              \
            float t3 = fmaf(-S2, (cc).w, (vv).w);                              \
            float m4 = fmaxf(fmaxf(t0, t1), fmaxf(t2, t3));                    \
            float nm = fmaxf(cm[q], m4);                                       \
            cs[q] = cs[q] * ex2f(cm[q] - nm)                                   \
                  + ((ex2f(t0 - nm) + ex2f(t1 - nm))                           \
                   + (ex2f(t2 - nm) + ex2f(t3 - nm)));                         \
            cm[q] = nm;                                                        \
        }
        CHAIN(0, c0, v0)
        CHAIN(1, c1, v1)
        CHAIN(2, c2, v2)
        CHAIN(3, c3, v3)
#undef CHAIN
    }

    // merge the 4 chains
    float mA = fmaxf(cm[0], cm[1]);
    float sA = cs[0] * ex2f(cm[0] - mA) + cs[1] * ex2f(cm[1] - mA);
    float mB = fmaxf(cm[2], cm[3]);
    float sB = cs[2] * ex2f(cm[2] - mB) + cs[3] * ex2f(cm[3] - mB);
    float m  = fmaxf(mA, mB);
    float s  = sA * ex2f(mA - m) + sB * ex2f(mB - m);

#pragma unroll
    for (int o = 16; o; o >>= 1) {
        float mo = __shfl_xor_sync(0xffffffffu, m, o);
        float so = __shfl_xor_sync(0xffffffffu, s, o);
        float nm = fmaxf(m, mo);
        s = s * ex2f(m - nm) + so * ex2f(mo - nm);
        m = nm;
    }
    if (l == 0) {
        float lse  = (m + lg2f(s)) * LN2;          // natural-log lse
        float pnew = EPSV * (LOG_MUV - lse);
        if (track_err) {
            float du = fabsf(pnew - mine[r]);
            atomicAdd(&blkerr, du);
        }
        mine[r] = pnew;
    }
    if (track_err) {
        __syncthreads();
        if (tid == 0) atomicAdd(&g_err[it], blkerr);
    }
}

// ---------------------------------------------------------------------------
// Epilogue: pi = exp((u_i + v_j - C_ij)/eps), cost[b] = sum pi*C
// ---------------------------------------------------------------------------
__global__ void __launch_bounds__(256) k_pi(const float* __restrict__ C,
                                            float* __restrict__ pi,
                                            float* __restrict__ cost) {
    __shared__ float blkcost;
    if (threadIdx.x == 0) blkcost = 0.0f;
    __syncthreads();

    int warp = (blockIdx.x << 3) + (threadIdx.x >> 5);
    int lane = threadIdx.x & 31;
    int r = warp;
    int b = r >> 11;

    float u = g_u[r];
    const float4* Cr = reinterpret_cast<const float4*>(C + (size_t)r * NPTS);
    const float4* Vr = reinterpret_cast<const float4*>(g_v + (b << 11));
    float4* Pr = reinterpret_cast<float4*>(pi + (size_t)r * NPTS);

    float acc = 0.0f;
#pragma unroll 4
    for (int k = lane; k < NPTS / 4; k += 32) {
        float4 c = Cr[k];
        float4 v = Vr[k];
        float4 p;
        p.x = ex2f((u + v.x - c.x) * S2);
        p.y = ex2f((u + v.y - c.y) * S2);
        p.z = ex2f((u + v.z - c.z) * S2);
        p.w = ex2f((u + v.w - c.w) * S2);
        Pr[k] = p;
        acc += p.x * c.x + p.y * c.y + p.z * c.z + p.w * c.w;
    }
#pragma unroll
    for (int o = 16; o; o >>= 1) acc += __shfl_xor_sync(0xffffffffu, acc, o);
    if (lane == 0) atomicAdd(&blkcost, acc);
    __syncthreads();
    if (threadIdx.x == 0) atomicAdd(&cost[b], blkcost);
}

// ---------------------------------------------------------------------------
// Launch: init -> cost(+CT) -> dummy -> 100 x (u-sweep over C, v-sweep over CT)
// -> pi. Output layout (tuple order): cost[8] | pi | C.
// ---------------------------------------------------------------------------
extern "C" void kernel_launch(void* const* d_in, const int* in_sizes, int n_in,
                              void* d_out, int out_size) {
    const float* x = (const float*)d_in[0];
    const float* y = (const float*)d_in[1];
    float* out  = (float*)d_out;
    float* cost = out;
    float* pi   = out + NBATCH;
    float* C    = out + NBATCH + NMAT;

    float* ct;
    cudaGetSymbolAddress((void**)&ct, g_ct);
    float* u;
    cudaGetSymbolAddress((void**)&u, g_u);
    float* v;
    cudaGetSymbolAddress((void**)&v, g_v);

    k_init<<<64, 256>>>(cost);
    k_cost<<<NBATCH * 32 * 32, 256>>>(x, y, C);
    k_dummy<<<1, 32>>>();   // keeps ncu capture slot on k_sweep
    for (int it = 0; it < MAX_IT; it++) {
        k_sweep<<<NROWS / 8, 256>>>(C,  v, u, it, 1);   // u update (tracks err)
        k_sweep<<<NROWS / 8, 256>>>(ct, u, v, it, 0);   // v update
    }
    k_pi<<<NROWS / 8, 256>>>(C, pi, cost);
}

// round 11
// speedup vs baseline: 1.2479x; 1.0825x over previous
#include <cuda_runtime.h>
#include <math.h>

// Problem constants
#define NBATCH 8
#define NPTS   2048
#define NFEAT  32
#define NROWS  (NBATCH * NPTS)                       // 16384
#define NMAT   ((size_t)NBATCH * NPTS * NPTS)        // 33554432
#define MAX_IT 100

// eps = 0.1 ; log2-domain scale: (1/eps) * log2(e)
#define S2   14.4269504088896341f
#define LN2  0.6931471805599453f
#define EPSV 0.1f
#define LOG_MUV (logf(1.0f / 2048.0f + 1e-8f))      // == log_nu (N == M)
#define ERR_THRESH_SUM 0.8f

// Scratch (__device__ globals; no allocation allowed)
__device__ __align__(16) float g_u[NROWS];
__device__ __align__(16) float g_v[NROWS];
__device__ float g_err[MAX_IT];
__device__ __align__(16) float g_ct[NMAT];           // 128 MB transposed cost

__device__ __forceinline__ float ex2f(float x) {
    float y;
    asm("ex2.approx.ftz.f32 %0, %1;" : "=f"(y) : "f"(x));
    return y;
}
__device__ __forceinline__ float lg2f(float x) {
    float y;
    asm("lg2.approx.ftz.f32 %0, %1;" : "=f"(y) : "f"(x));
    return y;
}

// ---------------------------------------------------------------------------
// Init
// ---------------------------------------------------------------------------
__global__ void k_init(float* __restrict__ cost) {
    int t = blockIdx.x * blockDim.x + threadIdx.x;
    int n = gridDim.x * blockDim.x;
    for (int i = t; i < NROWS; i += n) {
        g_u[i] = 0.0f;
        g_v[i] = 0.0f;
    }
    if (t < MAX_IT) g_err[t] = 0.0f;
    if (t < NBATCH) cost[t] = 0.0f;
}

// Dummy no-op: keeps the ncu capture slot aligned onto k_sweep.
__global__ void k_dummy() {}

// ---------------------------------------------------------------------------
// Cost matrix: C[b,i,j] = sum_d (x[b,i,d] - y[b,j,d])^2 ; also writes CT = C^T.
// ---------------------------------------------------------------------------
__global__ void __launch_bounds__(256) k_cost(const float* __restrict__ x,
                                              const float* __restrict__ y,
                                              float* __restrict__ C) {
    __shared__ float xs[NFEAT * 65];
    __shared__ float ys[NFEAT * 65];

    int tile = blockIdx.x;          // 8192 tiles of 64x64
    int b  = tile >> 10;
    int ti = (tile >> 5) & 31;
    int tj = tile & 31;
    int tid = threadIdx.x;

    const float* xb = x + ((size_t)b * NPTS + (size_t)ti * 64) * NFEAT;
    const float* yb = y + ((size_t)b * NPTS + (size_t)tj * 64) * NFEAT;

    for (int e = tid; e < 64 * NFEAT; e += 256) {
        int row = e >> 5;
        int d   = e & 31;
        xs[d * 65 + row] = xb[e];
        ys[d * 65 + row] = yb[e];
    }
    __syncthreads();

    int ri = (tid >> 4) << 2;
    int cj = (tid & 15) << 2;

    float acc[4][4];
#pragma unroll
    for (int a = 0; a < 4; a++)
#pragma unroll
        for (int c = 0; c < 4; c++) acc[a][c] = 0.0f;

#pragma unroll
    for (int d = 0; d < NFEAT; d++) {
        float xa[4], yv[4];
#pragma unroll
        for (int a = 0; a < 4; a++) xa[a] = xs[d * 65 + ri + a];
#pragma unroll
        for (int c = 0; c < 4; c++) yv[c] = ys[d * 65 + cj + c];
#pragma unroll
        for (int a = 0; a < 4; a++)
#pragma unroll
            for (int c = 0; c < 4; c++) {
                float diff = xa[a] - yv[c];
                acc[a][c] = fmaf(diff, diff, acc[a][c]);
            }
    }

    float* Cb = C + (size_t)b * NPTS * NPTS + (size_t)(ti * 64 + ri) * NPTS + (tj * 64 + cj);
#pragma unroll
    for (int a = 0; a < 4; a++) {
        float4 o = make_float4(acc[a][0], acc[a][1], acc[a][2], acc[a][3]);
        *reinterpret_cast<float4*>(Cb + (size_t)a * NPTS) = o;
    }

    // transposed copy: CT[b, j, i] = C[b, i, j]
    float* Tb = g_ct + (size_t)b * NPTS * NPTS + (size_t)(tj * 64 + cj) * NPTS + (ti * 64 + ri);
#pragma unroll
    for (int c = 0; c < 4; c++) {
        float4 o = make_float4(acc[0][c], acc[1][c], acc[2][c], acc[3][c]);
        *reinterpret_cast<float4*>(Tb + (size_t)c * NPTS) = o;
    }
}

// ---------------------------------------------------------------------------
// One Sinkhorn half-step (generic over u/v by pointer swap):
//   mine[r] = eps * (log_mu - lse_j((oth[j] - M[r, j]) / eps))
// M row-major for this sweep (C for the u-pass, CT for the v-pass).
// Block = 256 threads (8 warps), warp per row, 8 rows per block (R8 shape).
// Dual independent online-LSE chains for MUFU ILP; grouped 8-wide ex2.
// __launch_bounds__(256, 7): cap regs at 36 -> 7 blocks/SM = 56 warps (87%).
// track_err != 0: accumulate sum |mine_new - mine_old| into g_err[it].
// Early freeze: g_err[it-1] < thresh (sticky; frozen iters leave g_err = 0).
// ---------------------------------------------------------------------------
__global__ void __launch_bounds__(256, 7) k_sweep(const float* __restrict__ M,
                                                  const float* __restrict__ oth,
                                                  float* __restrict__ mine,
                                                  int it, int track_err) {
    if (it > 0 && g_err[it - 1] < ERR_THRESH_SUM) return;

    __shared__ float oS2[NPTS];          // 8 KB : other potential * S2
    __shared__ float blkerr;

    int blk = blockIdx.x;                // 2048 blocks, 8 rows each
    int b   = blk >> 8;
    int tid = threadIdx.x;
    int w   = tid >> 5;
    int l   = tid & 31;

    const float4* og  = reinterpret_cast<const float4*>(oth + (b << 11));
    float4*       os4 = reinterpret_cast<float4*>(oS2);
#pragma unroll
    for (int k = 0; k < 2; k++) {
        float4 t = og[tid + (k << 8)];
        t.x *= S2; t.y *= S2; t.z *= S2; t.w *= S2;
        os4[tid + (k << 8)] = t;
    }
    if (tid == 0) blkerr = 0.0f;
    __syncthreads();

    int r = (blk << 3) + w;              // global row index
    const float4* Mr = reinterpret_cast<const float4*>(M + ((size_t)r << 11));

    float m0 = -1e30f, s0 = 0.0f, m1 = -1e30f, s1 = 0.0f;
#pragma unroll
    for (int g = 0; g < 8; g++) {
        int idx = l + (g << 6);
        float4 c0 = Mr[idx];
        float4 c1 = Mr[idx + 32];
        float4 v0 = os4[idx];
        float4 v1 = os4[idx + 32];
        float t0 = fmaf(-S2, c0.x, v0.x);
        float t1 = fmaf(-S2, c0.y, v0.y);
        float t2 = fmaf(-S2, c0.z, v0.z);
        float t3 = fmaf(-S2, c0.w, v0.w);
        float t4 = fmaf(-S2, c1.x, v1.x);
        float t5 = fmaf(-S2, c1.y, v1.y);
        float t6 = fmaf(-S2, c1.z, v1.z);
        float t7 = fmaf(-S2, c1.w, v1.w);
        // chain 0 handles the first 4, chain 1 the second 4 (independent)
        float mA = fmaxf(fmaxf(t0, t1), fmaxf(t2, t3));
        float n0 = fmaxf(m0, mA);
        s0 = s0 * ex2f(m0 - n0)
           + ((ex2f(t0 - n0) + ex2f(t1 - n0)) + (ex2f(t2 - n0) + ex2f(t3 - n0)));
        m0 = n0;
        float mB = fmaxf(fmaxf(t4, t5), fmaxf(t6, t7));
        float n1 = fmaxf(m1, mB);
        s1 = s1 * ex2f(m1 - n1)
           + ((ex2f(t4 - n1) + ex2f(t5 - n1)) + (ex2f(t6 - n1) + ex2f(t7 - n1)));
        m1 = n1;
    }
    float m = fmaxf(m0, m1);
    float s = s0 * ex2f(m0 - m) + s1 * ex2f(m1 - m);
#pragma unroll
    for (int o = 16; o; o >>= 1) {
        float mo = __shfl_xor_sync(0xffffffffu, m, o);
        float so = __shfl_xor_sync(0xffffffffu, s, o);
        float nm = fmaxf(m, mo);
        s = s * ex2f(m - nm) + so * ex2f(mo - nm);
        m = nm;
    }
    if (l == 0) {
        float lse  = (m + lg2f(s)) * LN2;          // natural-log lse
        float pnew = EPSV * (LOG_MUV - lse);
        if (track_err) {
            float du = fabsf(pnew - mine[r]);
            atomicAdd(&blkerr, du);
        }
        mine[r] = pnew;
    }
    if (track_err) {
        __syncthreads();
        if (tid == 0) atomicAdd(&g_err[it], blkerr);
    }
}

// ---------------------------------------------------------------------------
// Epilogue: pi = exp((u_i + v_j - C_ij)/eps), cost[b] = sum pi*C
// ---------------------------------------------------------------------------
__global__ void __launch_bounds__(256) k_pi(const float* __restrict__ C,
                                            float* __restrict__ pi,
                                            float* __restrict__ cost) {
    __shared__ float blkcost;
    if (threadIdx.x == 0) blkcost = 0.0f;
    __syncthreads();

    int warp = (blockIdx.x << 3) + (threadIdx.x >> 5);
    int lane = threadIdx.x & 31;
    int r = warp;
    int b = r >> 11;

    float u = g_u[r];
    const float4* Cr = reinterpret_cast<const float4*>(C + (size_t)r * NPTS);
    const float4* Vr = reinterpret_cast<const float4*>(g_v + (b << 11));
    float4* Pr = reinterpret_cast<float4*>(pi + (size_t)r * NPTS);

    float acc = 0.0f;
#pragma unroll 4
    for (int k = lane; k < NPTS / 4; k += 32) {
        float4 c = Cr[k];
        float4 v = Vr[k];
        float4 p;
        p.x = ex2f((u + v.x - c.x) * S2);
        p.y = ex2f((u + v.y - c.y) * S2);
        p.z = ex2f((u + v.z - c.z) * S2);
        p.w = ex2f((u + v.w - c.w) * S2);
        Pr[k] = p;
        acc += p.x * c.x + p.y * c.y + p.z * c.z + p.w * c.w;
    }
#pragma unroll
    for (int o = 16; o; o >>= 1) acc += __shfl_xor_sync(0xffffffffu, acc, o);
    if (lane == 0) atomicAdd(&blkcost, acc);
    __syncthreads();
    if (threadIdx.x == 0) atomicAdd(&cost[b], blkcost);
}

// ---------------------------------------------------------------------------
// Launch: init -> cost(+CT) -> dummy -> 100 x (u-sweep over C, v-sweep over CT)
// -> pi. Output layout (tuple order): cost[8] | pi | C.
// ---------------------------------------------------------------------------
extern "C" void kernel_launch(void* const* d_in, const int* in_sizes, int n_in,
                              void* d_out, int out_size) {
    const float* x = (const float*)d_in[0];
    const float* y = (const float*)d_in[1];
    float* out  = (float*)d_out;
    float* cost = out;
    float* pi   = out + NBATCH;
    float* C    = out + NBATCH + NMAT;

    float* ct;
    cudaGetSymbolAddress((void**)&ct, g_ct);
    float* u;
    cudaGetSymbolAddress((void**)&u, g_u);
    float* v;
    cudaGetSymbolAddress((void**)&v, g_v);

    k_init<<<64, 256>>>(cost);
    k_cost<<<NBATCH * 32 * 32, 256>>>(x, y, C);
    k_dummy<<<1, 32>>>();   // keeps ncu capture slot on k_sweep
    for (int it = 0; it < MAX_IT; it++) {
        k_sweep<<<NROWS / 8, 256>>>(C,  v, u, it, 1);   // u update (tracks err)
        k_sweep<<<NROWS / 8, 256>>>(ct, u, v, it, 0);   // v update
    }
    k_pi<<<NROWS / 8, 256>>>(C, pi, cost);
}

// round 12
// speedup vs baseline: 1.4442x; 1.1574x over previous
#include <cuda_runtime.h>
#include <math.h>

// Problem constants
#define NBATCH 8
#define NPTS   2048
#define NFEAT  32
#define NROWS  (NBATCH * NPTS)                       // 16384
#define NMAT   ((size_t)NBATCH * NPTS * NPTS)        // 33554432
#define MAX_IT 100

// eps = 0.1 ; log2-domain scale: (1/eps) * log2(e)
#define S2   14.4269504088896341f
#define LN2  0.6931471805599453f
#define EPSV 0.1f
#define LOG_MUV (logf(1.0f / 2048.0f + 1e-8f))      // == log_nu (N == M)
#define ERR_THRESH_SUM 0.8f

// Scratch (__device__ globals; no allocation allowed)
__device__ __align__(16) float g_u[NROWS];
__device__ __align__(16) float g_v[NROWS];
__device__ float g_err[MAX_IT];

__device__ __forceinline__ float ex2f(float x) {
    float y;
    asm("ex2.approx.ftz.f32 %0, %1;" : "=f"(y) : "f"(x));
    return y;
}
__device__ __forceinline__ float lg2f(float x) {
    float y;
    asm("lg2.approx.ftz.f32 %0, %1;" : "=f"(y) : "f"(x));
    return y;
}

// ---------------------------------------------------------------------------
// Init
// ---------------------------------------------------------------------------
__global__ void k_init(float* __restrict__ cost) {
    int t = blockIdx.x * blockDim.x + threadIdx.x;
    int n = gridDim.x * blockDim.x;
    for (int i = t; i < NROWS; i += n) {
        g_u[i] = 0.0f;
        g_v[i] = 0.0f;
    }
    if (t < MAX_IT) g_err[t] = 0.0f;
    if (t < NBATCH) cost[t] = 0.0f;
}

// Dummy no-op: keeps the ncu capture slot aligned onto the first u-sweep.
__global__ void k_dummy() {}

// ---------------------------------------------------------------------------
// Cost matrix: C[b,i,j] = sum_d (x[b,i,d] - y[b,j,d])^2   (no transposed copy)
// ---------------------------------------------------------------------------
__global__ void __launch_bounds__(256) k_cost(const float* __restrict__ x,
                                              const float* __restrict__ y,
                                              float* __restrict__ C) {
    __shared__ float xs[NFEAT * 65];
    __shared__ float ys[NFEAT * 65];

    int tile = blockIdx.x;          // 8192 tiles of 64x64
    int b  = tile >> 10;
    int ti = (tile >> 5) & 31;
    int tj = tile & 31;
    int tid = threadIdx.x;

    const float* xb = x + ((size_t)b * NPTS + (size_t)ti * 64) * NFEAT;
    const float* yb = y + ((size_t)b * NPTS + (size_t)tj * 64) * NFEAT;

    for (int e = tid; e < 64 * NFEAT; e += 256) {
        int row = e >> 5;
        int d   = e & 31;
        xs[d * 65 + row] = xb[e];
        ys[d * 65 + row] = yb[e];
    }
    __syncthreads();

    int ri = (tid >> 4) << 2;
    int cj = (tid & 15) << 2;

    float acc[4][4];
#pragma unroll
    for (int a = 0; a < 4; a++)
#pragma unroll
        for (int c = 0; c < 4; c++) acc[a][c] = 0.0f;

#pragma unroll
    for (int d = 0; d < NFEAT; d++) {
        float xa[4], yv[4];
#pragma unroll
        for (int a = 0; a < 4; a++) xa[a] = xs[d * 65 + ri + a];
#pragma unroll
        for (int c = 0; c < 4; c++) yv[c] = ys[d * 65 + cj + c];
#pragma unroll
        for (int a = 0; a < 4; a++)
#pragma unroll
            for (int c = 0; c < 4; c++) {
                float diff = xa[a] - yv[c];
                acc[a][c] = fmaf(diff, diff, acc[a][c]);
            }
    }

    float* Cb = C + (size_t)b * NPTS * NPTS + (size_t)(ti * 64 + ri) * NPTS + (tj * 64 + cj);
#pragma unroll
    for (int a = 0; a < 4; a++) {
        float4 o = make_float4(acc[a][0], acc[a][1], acc[a][2], acc[a][3]);
        *reinterpret_cast<float4*>(Cb + (size_t)a * NPTS) = o;
    }
}

// ---------------------------------------------------------------------------
// u-sweep (row LSE over C, row-major). R11 shape: 256 thr, warp per row,
// dual online-LSE chains, __launch_bounds__(256,7) -> 32 regs, 87% occ.
// Batches ascending (bid order): starts on b0, which the previous v-sweep
// finished with -> L2 hits.
// ---------------------------------------------------------------------------
__global__ void __launch_bounds__(256, 7) k_sweep(const float* __restrict__ M,
                                                  const float* __restrict__ oth,
                                                  float* __restrict__ mine,
                                                  int it, int track_err) {
    if (it > 0 && g_err[it - 1] < ERR_THRESH_SUM) return;

    __shared__ float oS2[NPTS];          // 8 KB : other potential * S2
    __shared__ float blkerr;

    int blk = blockIdx.x;                // 2048 blocks, 8 rows each
    int b   = blk >> 8;
    int tid = threadIdx.x;
    int w   = tid >> 5;
    int l   = tid & 31;

    const float4* og  = reinterpret_cast<const float4*>(oth + (b << 11));
    float4*       os4 = reinterpret_cast<float4*>(oS2);
#pragma unroll
    for (int k = 0; k < 2; k++) {
        float4 t = og[tid + (k << 8)];
        t.x *= S2; t.y *= S2; t.z *= S2; t.w *= S2;
        os4[tid + (k << 8)] = t;
    }
    if (tid == 0) blkerr = 0.0f;
    __syncthreads();

    int r = (blk << 3) + w;              // global row index
    const float4* Mr = reinterpret_cast<const float4*>(M + ((size_t)r << 11));

    float m0 = -1e30f, s0 = 0.0f, m1 = -1e30f, s1 = 0.0f;
#pragma unroll
    for (int g = 0; g < 8; g++) {
        int idx = l + (g << 6);
        float4 c0 = Mr[idx];
        float4 c1 = Mr[idx + 32];
        float4 v0 = os4[idx];
        float4 v1 = os4[idx + 32];
        float t0 = fmaf(-S2, c0.x, v0.x);
        float t1 = fmaf(-S2, c0.y, v0.y);
        float t2 = fmaf(-S2, c0.z, v0.z);
        float t3 = fmaf(-S2, c0.w, v0.w);
        float t4 = fmaf(-S2, c1.x, v1.x);
        float t5 = fmaf(-S2, c1.y, v1.y);
        float t6 = fmaf(-S2, c1.z, v1.z);
        float t7 = fmaf(-S2, c1.w, v1.w);
        float mA = fmaxf(fmaxf(t0, t1), fmaxf(t2, t3));
        float n0 = fmaxf(m0, mA);
        s0 = s0 * ex2f(m0 - n0)
           + ((ex2f(t0 - n0) + ex2f(t1 - n0)) + (ex2f(t2 - n0) + ex2f(t3 - n0)));
        m0 = n0;
        float mB = fmaxf(fmaxf(t4, t5), fmaxf(t6, t7));
        float n1 = fmaxf(m1, mB);
        s1 = s1 * ex2f(m1 - n1)
           + ((ex2f(t4 - n1) + ex2f(t5 - n1)) + (ex2f(t6 - n1) + ex2f(t7 - n1)));
        m1 = n1;
    }
    float m = fmaxf(m0, m1);
    float s = s0 * ex2f(m0 - m) + s1 * ex2f(m1 - m);
#pragma unroll
    for (int o = 16; o; o >>= 1) {
        float mo = __shfl_xor_sync(0xffffffffu, m, o);
        float so = __shfl_xor_sync(0xffffffffu, s, o);
        float nm = fmaxf(m, mo);
        s = s * ex2f(m - nm) + so * ex2f(mo - nm);
        m = nm;
    }
    if (l == 0) {
        float lse  = (m + lg2f(s)) * LN2;
        float pnew = EPSV * (LOG_MUV - lse);
        if (track_err) {
            float du = fabsf(pnew - mine[r]);
            atomicAdd(&blkerr, du);
        }
        mine[r] = pnew;
    }
    if (track_err) {
        __syncthreads();
        if (tid == 0) atomicAdd(&g_err[it], blkerr);
    }
}

// ---------------------------------------------------------------------------
// v-sweep: column LSE over C itself (no transposed copy).
//   v_j = eps * (log_nu - lse_i((u_i - C_ij)/eps))
// Block = 512 threads (16 warps), 32 columns; warp w owns rows [w*128, +128).
// Thread = one column strand: per step loads 8 rows (8 independent coalesced
// LDG.32s -> 8 lines in flight per warp), dual online-LSE chains.
// 512 blocks = one wave; batches DESCENDING so the sweep ends on b0, which
// the next u-sweep (ascending) reads first -> circular L2 reuse of the
// single 128 MB C array (L2 = 126 MB).
// ---------------------------------------------------------------------------
__global__ void __launch_bounds__(512) k_vcol(const float* __restrict__ C, int it) {
    if (it > 0 && g_err[it - 1] < ERR_THRESH_SUM) return;

    __shared__ float uS2_s[NPTS];        // 8 KB : u * S2
    __shared__ float pm_s[16 * 32];      // per-warp column partial max
    __shared__ float ps_s[16 * 32];      // per-warp column partial sum

    int blk = blockIdx.x;                // 512 blocks
    int b   = 7 - (blk >> 6);            // descending batches
    int jg  = blk & 63;                  // column group (32 cols)
    int tid = threadIdx.x;
    int w   = tid >> 5;
    int l   = tid & 31;

    const float4* ug  = reinterpret_cast<const float4*>(g_u + (b << 11));
    float4*       us4 = reinterpret_cast<float4*>(uS2_s);
    {
        float4 t = ug[tid];
        t.x *= S2; t.y *= S2; t.z *= S2; t.w *= S2;
        us4[tid] = t;
    }
    __syncthreads();

    int j = (jg << 5) + l;               // this thread's column
    const float* Cb = C + ((size_t)b << 22) + j;

    float m0 = -1e30f, s0 = 0.0f, m1 = -1e30f, s1 = 0.0f;
    int i0 = w << 7;                     // warp's 128-row segment
#pragma unroll 2
    for (int g = 0; g < 16; g++) {
        int i = i0 + (g << 3);
        const float* Ci = Cb + ((size_t)i << 11);
        // 8 coalesced loads (one 128B line per row per warp), issued together
        float c0 = Ci[0 << 11];
        float c1 = Ci[1 << 11];
        float c2 = Ci[2 << 11];
        float c3 = Ci[3 << 11];
        float c4 = Ci[4 << 11];
        float c5 = Ci[5 << 11];
        float c6 = Ci[6 << 11];
        float c7 = Ci[7 << 11];
        float t0 = fmaf(-S2, c0, uS2_s[i + 0]);
        float t1 = fmaf(-S2, c1, uS2_s[i + 1]);
        float t2 = fmaf(-S2, c2, uS2_s[i + 2]);
        float t3 = fmaf(-S2, c3, uS2_s[i + 3]);
        float t4 = fmaf(-S2, c4, uS2_s[i + 4]);
        float t5 = fmaf(-S2, c5, uS2_s[i + 5]);
        float t6 = fmaf(-S2, c6, uS2_s[i + 6]);
        float t7 = fmaf(-S2, c7, uS2_s[i + 7]);
        float mA = fmaxf(fmaxf(t0, t1), fmaxf(t2, t3));
        float n0 = fmaxf(m0, mA);
        s0 = s0 * ex2f(m0 - n0)
           + ((ex2f(t0 - n0) + ex2f(t1 - n0)) + (ex2f(t2 - n0) + ex2f(t3 - n0)));
        m0 = n0;
        float mB = fmaxf(fmaxf(t4, t5), fmaxf(t6, t7));
        float n1 = fmaxf(m1, mB);
        s1 = s1 * ex2f(m1 - n1)
           + ((ex2f(t4 - n1) + ex2f(t5 - n1)) + (ex2f(t6 - n1) + ex2f(t7 - n1)));
        m1 = n1;
    }
    float m = fmaxf(m0, m1);
    float s = s0 * ex2f(m0 - m) + s1 * ex2f(m1 - m);
    pm_s[(w << 5) + l] = m;
    ps_s[(w << 5) + l] = s;
    __syncthreads();

    if (w == 0) {
        float mm = pm_s[l], ss = ps_s[l];
#pragma unroll
        for (int k = 1; k < 16; k++) {
            float mo = pm_s[(k << 5) + l];
            float so = ps_s[(k << 5) + l];
            float nm = fmaxf(mm, mo);
            ss = ss * ex2f(mm - nm) + so * ex2f(mo - nm);
            mm = nm;
        }
        g_v[(b << 11) + j] = EPSV * (LOG_MUV - (mm + lg2f(ss)) * LN2);
    }
}

// ---------------------------------------------------------------------------
// Epilogue: pi = exp((u_i + v_j - C_ij)/eps), cost[b] = sum pi*C
// ---------------------------------------------------------------------------
__global__ void __launch_bounds__(256) k_pi(const float* __restrict__ C,
                                            float* __restrict__ pi,
                                            float* __restrict__ cost) {
    __shared__ float blkcost;
    if (threadIdx.x == 0) blkcost = 0.0f;
    __syncthreads();

    int warp = (blockIdx.x << 3) + (threadIdx.x >> 5);
    int lane = threadIdx.x & 31;
    int r = warp;
    int b = r >> 11;

    float u = g_u[r];
    const float4* Cr = reinterpret_cast<const float4*>(C + (size_t)r * NPTS);
    const float4* Vr = reinterpret_cast<const float4*>(g_v + (b << 11));
    float4* Pr = reinterpret_cast<float4*>(pi + (size_t)r * NPTS);

    float acc = 0.0f;
#pragma unroll 4
    for (int k = lane; k < NPTS / 4; k += 32) {
        float4 c = Cr[k];
        float4 v = Vr[k];
        float4 p;
        p.x = ex2f((u + v.x - c.x) * S2);
        p.y = ex2f((u + v.y - c.y) * S2);
        p.z = ex2f((u + v.z - c.z) * S2);
        p.w = ex2f((u + v.w - c.w) * S2);
        Pr[k] = p;
        acc += p.x * c.x + p.y * c.y + p.z * c.z + p.w * c.w;
    }
#pragma unroll
    for (int o = 16; o; o >>= 1) acc += __shfl_xor_sync(0xffffffffu, acc, o);
    if (lane == 0) atomicAdd(&blkcost, acc);
    __syncthreads();
    if (threadIdx.x == 0) atomicAdd(&cost[b], blkcost);
}

// ---------------------------------------------------------------------------
// Launch: init -> cost -> dummy -> 100 x (u-sweep rows of C, v-sweep cols of C)
// -> pi. Output layout (tuple order): cost[8] | pi | C.
// ---------------------------------------------------------------------------
extern "C" void kernel_launch(void* const* d_in, const int* in_sizes, int n_in,
                              void* d_out, int out_size) {
    const float* x = (const float*)d_in[0];
    const float* y = (const float*)d_in[1];
    float* out  = (float*)d_out;
    float* cost = out;
    float* pi   = out + NBATCH;
    float* C    = out + NBATCH + NMAT;

    float* u;
    cudaGetSymbolAddress((void**)&u, g_u);
    float* v;
    cudaGetSymbolAddress((void**)&v, g_v);

    k_init<<<64, 256>>>(cost);
    k_cost<<<NBATCH * 32 * 32, 256>>>(x, y, C);
    k_dummy<<<1, 32>>>();   // keeps ncu capture slot on the first u-sweep
    for (int it = 0; it < MAX_IT; it++) {
        k_sweep<<<NROWS / 8, 256>>>(C, v, u, it, 1);   // u update (tracks err)
        k_vcol<<<512, 512>>>(C, it);                   // v update, column LSE
    }
    k_pi<<<NROWS / 8, 256>>>(C, pi, cost);
}